// round 11
// baseline (speedup 1.0000x reference)
#include <cuda_runtime.h>
#include <cuda_fp16.h>

#define NN 65536
#define EE 2097152
#define EPAD (4 * EE + 16 * NN)
#define HID 32
#define NG 8
#define OC 33
#define ISZ 8192

// ---------------- scratch (static device allocations only) ----------------
__device__ int   g_deg[NN];
__device__ float g_dinv[NN];
__device__ int   g_cnt[NN];      // raw dst-degree
__device__ int   g_cnt8[NN];     // quad-equalized, padded to multiple of 8
__device__ int   g_rowptr[NN];   // exclusive scan of padded counts (mult of 8)
__device__ int   g_wp[NN];
__device__ int   g_bsum[64];
__device__ __align__(16) int g_esrc[EPAD];   // src-only edges (norm factored out)
// scalar t values (fp32) and premultiplied gather values u = dinv*t (fp32)
__device__ float g_s1[NN], g_s2[NN], g_s3[NN], g_s4[NN];
__device__ float g_ux[NN + 8], g_u1[NN + 8], g_u2[NN + 8], g_u3[NN + 8], g_u4[NN + 8];
__device__ __align__(128) float g_H[NN * HID];
__device__ __align__(128) float g_A[NN * HID];
__device__ __align__(128) float g_B[NN * HID];
__device__ __align__(128) float g_C[NN * HID];
__device__ __align__(128) float g_O[NN * HID];
// fp16 premultiplied gather mirrors: row i < NN holds dinv[i]*t[i]; rows >= NN
// are NEVER written -> remain statically zero-initialized (pad sentinel src=NN)
__device__ __align__(128) __half g_Hh[(NN + 8) * HID];
__device__ __align__(128) __half g_Ah[(NN + 8) * HID];
__device__ __align__(128) __half g_Bh[(NN + 8) * HID];
__device__ __align__(128) __half g_Ch[(NN + 8) * HID];

// ---------------- CSR build ----------------
__global__ void k_zero() {
    int i = blockIdx.x * blockDim.x + threadIdx.x;
    if (i < NN) { g_deg[i] = 0; g_cnt[i] = 0; }
}

__global__ void k_hist(const int* __restrict__ ei) {
    int e = blockIdx.x * blockDim.x + threadIdx.x;
    if (e < EE) {
        atomicAdd(&g_deg[ei[e]], 1);        // degree by src
        atomicAdd(&g_cnt[ei[EE + e]], 1);   // histogram by dst
    }
}

// block-level inclusive scan of quad-equalized padded counts + fused dinv.
// Nodes (4k..4k+3) all get align8(max cnt over the quad) slots so the
// quad-node prop loop needs no per-node predication.
__global__ void k_scan1() {
    __shared__ int wsum[32];
    int t = threadIdx.x, b = blockIdx.x;
    int i = b * 1024 + t;
    int lane = t & 31, w = t >> 5;
    int d = g_deg[i];
    g_dinv[i] = (d > 0) ? rsqrtf((float)d) : 0.0f;

    int q = i & ~3;                         // quad base (same block: 1024 % 4 == 0)
    int c0 = g_cnt[q], c1 = g_cnt[q + 1], c2 = g_cnt[q + 2], c3 = g_cnt[q + 3];
    int cm = max(max(c0, c1), max(c2, c3));
    int cntp = (cm + 7) & ~7;
    g_cnt8[i] = cntp;

    int x = cntp;
    #pragma unroll
    for (int o = 1; o < 32; o <<= 1) {
        int y = __shfl_up_sync(0xffffffffu, x, o);
        if (lane >= o) x += y;
    }
    if (lane == 31) wsum[w] = x;
    __syncthreads();
    if (w == 0) {
        int s = wsum[lane];
        #pragma unroll
        for (int o = 1; o < 32; o <<= 1) {
            int y = __shfl_up_sync(0xffffffffu, s, o);
            if (lane >= o) s += y;
        }
        wsum[lane] = s;
    }
    __syncthreads();
    int incl = x + (w > 0 ? wsum[w - 1] : 0);
    g_rowptr[i] = incl;                 // inclusive-within-block (temp)
    if (t == 1023) g_bsum[b] = incl;
}

// finalize rowptr (cross-block prefix inline), fill pad slots, compute u_x
__global__ void k_scan3(const float* __restrict__ x) {
    __shared__ int prefix;
    int i = blockIdx.x * 256 + threadIdx.x;
    if (threadIdx.x == 0) {
        int bchunk = blockIdx.x >> 2;   // 1024-node chunks
        int s = 0;
        for (int j = 0; j < bchunk; j++) s += g_bsum[j];
        prefix = s;
    }
    __syncthreads();
    int excl = g_rowptr[i] - g_cnt8[i] + prefix;   // multiple of 8
    g_rowptr[i] = excl;
    g_wp[i] = excl;
    g_ux[i] = g_dinv[i] * x[i];
    int c = g_cnt[i], cp = g_cnt8[i];
    for (int j = excl + c; j < excl + cp; j++) g_esrc[j] = NN;  // zero-row sentinel
}

__global__ void k_scatter(const int* __restrict__ ei) {
    int e = blockIdx.x * blockDim.x + threadIdx.x;
    if (e < EE) {
        int d = ei[EE + e];
        int pos = atomicAdd(&g_wp[d], 1);
        g_esrc[pos] = ei[e];
    }
}

// ---------------- layer 1 (scalar features, premultiplied gathers) ----------------
template <bool PREV>
__global__ void k_sprop(const float* __restrict__ uin,
                        const float* __restrict__ sprev,
                        float* __restrict__ sout,
                        float* __restrict__ usout) {
    int gw = (blockIdx.x * blockDim.x + threadIdx.x) >> 5;
    int lane = threadIdx.x & 31;
    int beg = g_rowptr[gw], c = g_cnt8[gw];
    float acc = 0.0f;
    for (int j = lane * 2; j < c; j += 64) {
        int2 s2 = *reinterpret_cast<const int2*>(g_esrc + beg + j);
        acc += __ldg(&uin[s2.x]) + __ldg(&uin[s2.y]);
    }
    #pragma unroll
    for (int o = 16; o; o >>= 1) acc += __shfl_xor_sync(0xffffffffu, acc, o);
    if (lane == 0) {
        float dd = g_dinv[gw];
        float p = -dd * acc;
        float tn = PREV ? (2.0f * p - sprev[gw]) : p;
        sout[gw] = tn;
        usout[gw] = dd * tn;
    }
}

// layer-1 combine + layer-2 init: h = relu(b1 + sum_k s_k*W1[k]); H=h; Hh=dinv*h; O = h @ W2[0]
__global__ void __launch_bounds__(256, 6) k_l1init(const float* __restrict__ x,
                                                   const float* __restrict__ W1,
                                                   const float* __restrict__ b1,
                                                   const float* __restrict__ W20) {
    __shared__ float Ws[1024];
    int tid = threadIdx.x;
    for (int j = tid; j < 1024; j += 256) Ws[j] = W20[j];
    __syncthreads();
    int gw = (blockIdx.x * 256 + tid) >> 5;
    int lane = tid & 31;
    float v = b1[lane]
            + x[gw]      * W1[lane]
            + g_s1[gw]   * W1[32 + lane]
            + g_s2[gw]   * W1[64 + lane]
            + g_s3[gw]   * W1[96 + lane]
            + g_s4[gw]   * W1[128 + lane];
    float h = fmaxf(v, 0.0f);
    g_H[gw * HID + lane] = h;
    g_Hh[gw * HID + lane] = __float2half(g_dinv[gw] * h);
    float oacc = 0.0f;
    #pragma unroll
    for (int j = 0; j < 32; j++)
        oacc = fmaf(__shfl_sync(0xffffffffu, h, j), Ws[j * 32 + lane], oacc);
    g_O[gw * HID + lane] = oacc;
}

// ---------------- layers 2/3 (32-wide), FOUR nodes per warp ----------------
// tin holds u = dinv*t (fp16). For each of the warp's four nodes:
// acc = sum u[src]; p = -dinv*acc; t_new = (PREV ? 2p - tprev : p);
// tout = t_new; touth = dinv*t_new; g_O += t_new @ Wk.
// Quad-equalized 8-padded lists -> branch-free loop, 32 independent gathers/iter.
template <bool PREV>
__global__ void __launch_bounds__(256, 3) k_prop32(const __half* __restrict__ tin,
                                                   const float* __restrict__ tprev,
                                                   float* __restrict__ tout,
                                                   __half* __restrict__ touth,
                                                   const float* __restrict__ Wk) {
    __shared__ float Ws[1024];
    int tid = threadIdx.x;
    for (int j = tid; j < 1024; j += 256) Ws[j] = Wk[j];
    __syncthreads();
    int warp = (blockIdx.x * 256 + tid) >> 5;
    int g0 = warp * 4, g1 = g0 + 1, g2 = g0 + 2, g3 = g0 + 3;
    int lane = tid & 31;
    const int4* p0 = reinterpret_cast<const int4*>(g_esrc + g_rowptr[g0]);
    const int4* p1 = reinterpret_cast<const int4*>(g_esrc + g_rowptr[g1]);
    const int4* p2 = reinterpret_cast<const int4*>(g_esrc + g_rowptr[g2]);
    const int4* p3 = reinterpret_cast<const int4*>(g_esrc + g_rowptr[g3]);
    int nIter = g_cnt8[g0] >> 3;            // equal across the quad
    float acc0 = 0.0f, acc1 = 0.0f, acc2 = 0.0f, acc3 = 0.0f;
    for (int it = 0; it < nIter; it++) {
        int4 ea0 = p0[0], eb0 = p0[1];
        int4 ea1 = p1[0], eb1 = p1[1];
        int4 ea2 = p2[0], eb2 = p2[1];
        int4 ea3 = p3[0], eb3 = p3[1];
        p0 += 2; p1 += 2; p2 += 2; p3 += 2;
        __half a0 = __ldg(&tin[ea0.x * HID + lane]);
        __half a1 = __ldg(&tin[ea0.y * HID + lane]);
        __half a2 = __ldg(&tin[ea0.z * HID + lane]);
        __half a3 = __ldg(&tin[ea0.w * HID + lane]);
        __half a4 = __ldg(&tin[eb0.x * HID + lane]);
        __half a5 = __ldg(&tin[eb0.y * HID + lane]);
        __half a6 = __ldg(&tin[eb0.z * HID + lane]);
        __half a7 = __ldg(&tin[eb0.w * HID + lane]);
        __half b0 = __ldg(&tin[ea1.x * HID + lane]);
        __half b1 = __ldg(&tin[ea1.y * HID + lane]);
        __half b2 = __ldg(&tin[ea1.z * HID + lane]);
        __half b3 = __ldg(&tin[ea1.w * HID + lane]);
        __half b4 = __ldg(&tin[eb1.x * HID + lane]);
        __half b5 = __ldg(&tin[eb1.y * HID + lane]);
        __half b6 = __ldg(&tin[eb1.z * HID + lane]);
        __half b7 = __ldg(&tin[eb1.w * HID + lane]);
        __half c0 = __ldg(&tin[ea2.x * HID + lane]);
        __half c1 = __ldg(&tin[ea2.y * HID + lane]);
        __half c2 = __ldg(&tin[ea2.z * HID + lane]);
        __half c3 = __ldg(&tin[ea2.w * HID + lane]);
        __half c4 = __ldg(&tin[eb2.x * HID + lane]);
        __half c5 = __ldg(&tin[eb2.y * HID + lane]);
        __half c6 = __ldg(&tin[eb2.z * HID + lane]);
        __half c7 = __ldg(&tin[eb2.w * HID + lane]);
        __half d0 = __ldg(&tin[ea3.x * HID + lane]);
        __half d1 = __ldg(&tin[ea3.y * HID + lane]);
        __half d2 = __ldg(&tin[ea3.z * HID + lane]);
        __half d3 = __ldg(&tin[ea3.w * HID + lane]);
        __half d4 = __ldg(&tin[eb3.x * HID + lane]);
        __half d5 = __ldg(&tin[eb3.y * HID + lane]);
        __half d6 = __ldg(&tin[eb3.z * HID + lane]);
        __half d7 = __ldg(&tin[eb3.w * HID + lane]);
        acc0 += ((__half2float(a0) + __half2float(a1))
               + (__half2float(a2) + __half2float(a3)))
              + ((__half2float(a4) + __half2float(a5))
               + (__half2float(a6) + __half2float(a7)));
        acc1 += ((__half2float(b0) + __half2float(b1))
               + (__half2float(b2) + __half2float(b3)))
              + ((__half2float(b4) + __half2float(b5))
               + (__half2float(b6) + __half2float(b7)));
        acc2 += ((__half2float(c0) + __half2float(c1))
               + (__half2float(c2) + __half2float(c3)))
              + ((__half2float(c4) + __half2float(c5))
               + (__half2float(c6) + __half2float(c7)));
        acc3 += ((__half2float(d0) + __half2float(d1))
               + (__half2float(d2) + __half2float(d3)))
              + ((__half2float(d4) + __half2float(d5))
               + (__half2float(d6) + __half2float(d7)));
    }
    float dd0 = g_dinv[g0], dd1 = g_dinv[g1], dd2 = g_dinv[g2], dd3 = g_dinv[g3];
    float tn0 = -dd0 * acc0, tn1 = -dd1 * acc1, tn2 = -dd2 * acc2, tn3 = -dd3 * acc3;
    if (PREV) {
        tn0 = 2.0f * tn0 - tprev[g0 * HID + lane];
        tn1 = 2.0f * tn1 - tprev[g1 * HID + lane];
        tn2 = 2.0f * tn2 - tprev[g2 * HID + lane];
        tn3 = 2.0f * tn3 - tprev[g3 * HID + lane];
    }
    tout[g0 * HID + lane] = tn0;
    tout[g1 * HID + lane] = tn1;
    tout[g2 * HID + lane] = tn2;
    tout[g3 * HID + lane] = tn3;
    touth[g0 * HID + lane] = __float2half(dd0 * tn0);
    touth[g1 * HID + lane] = __float2half(dd1 * tn1);
    touth[g2 * HID + lane] = __float2half(dd2 * tn2);
    touth[g3 * HID + lane] = __float2half(dd3 * tn3);
    float o0 = g_O[g0 * HID + lane];
    float o1 = g_O[g1 * HID + lane];
    float o2 = g_O[g2 * HID + lane];
    float o3 = g_O[g3 * HID + lane];
    #pragma unroll
    for (int j = 0; j < 32; j++) {
        float w = Ws[j * 32 + lane];
        o0 = fmaf(__shfl_sync(0xffffffffu, tn0, j), w, o0);
        o1 = fmaf(__shfl_sync(0xffffffffu, tn1, j), w, o1);
        o2 = fmaf(__shfl_sync(0xffffffffu, tn2, j), w, o2);
        o3 = fmaf(__shfl_sync(0xffffffffu, tn3, j), w, o3);
    }
    g_O[g0 * HID + lane] = o0;
    g_O[g1 * HID + lane] = o1;
    g_O[g2 * HID + lane] = o2;
    g_O[g3 * HID + lane] = o3;
}

// finalize layer L + init layer L+1: h = relu(O + b); H=h; Hh=dinv*h; O = h @ Wn0
__global__ void __launch_bounds__(256, 6) k_finit(const float* __restrict__ b,
                                                  const float* __restrict__ Wn0) {
    __shared__ float Ws[1024];
    int tid = threadIdx.x;
    for (int j = tid; j < 1024; j += 256) Ws[j] = Wn0[j];
    __syncthreads();
    int gw = (blockIdx.x * 256 + tid) >> 5;
    int lane = tid & 31;
    float h = fmaxf(g_O[gw * HID + lane] + b[lane], 0.0f);
    g_H[gw * HID + lane] = h;
    g_Hh[gw * HID + lane] = __float2half(g_dinv[gw] * h);
    float oacc = 0.0f;
    #pragma unroll
    for (int j = 0; j < 32; j++)
        oacc = fmaf(__shfl_sync(0xffffffffu, h, j), Ws[j * 32 + lane], oacc);
    g_O[gw * HID + lane] = oacc;
}

// ---------------- final linear: (8, 262144) @ (262144, 33) + bl ----------------
// layer-3 bias b3 folded in (h = O + b3); no separate finalize pass.
__global__ void k_obias(const float* __restrict__ bl, float* __restrict__ out) {
    int i = threadIdx.x;
    if (i < NG * OC) out[i] = bl[i % OC];
}

__global__ void __launch_bounds__(288) k_linear(const float* __restrict__ Wl,
                                                const float* __restrict__ b3,
                                                float* __restrict__ out) {
    __shared__ float Ws[128 * OC];   // 16896 B
    __shared__ float hs[NG * 128];   //  4096 B
    int t = threadIdx.x;
    int i0 = blockIdx.x * 128;
    for (int j = t; j < 128 * OC; j += 288) Ws[j] = Wl[i0 * OC + j];
    for (int j = t; j < NG * 128; j += 288) {
        int g = j >> 7, ii = j & 127;
        hs[j] = g_O[g * (ISZ * HID) + i0 + ii] + b3[(i0 + ii) & 31];
    }
    __syncthreads();
    if (t < NG * OC) {
        int g = t / OC, o = t % OC;
        float acc = 0.0f;
        #pragma unroll 8
        for (int ii = 0; ii < 128; ii++)
            acc = fmaf(hs[g * 128 + ii], Ws[ii * OC + o], acc);
        atomicAdd(&out[g * OC + o], acc);
    }
}

// ---------------- host ----------------
extern "C" void kernel_launch(void* const* d_in, const int* in_sizes, int n_in,
                              void* d_out, int out_size) {
    const float* x  = (const float*)d_in[0];
    const int*   ei = (const int*)  d_in[1];
    const float* W1 = (const float*)d_in[3];
    const float* b1 = (const float*)d_in[4];
    const float* W2 = (const float*)d_in[5];
    const float* b2 = (const float*)d_in[6];
    const float* W3 = (const float*)d_in[7];
    const float* b3 = (const float*)d_in[8];
    const float* Wl = (const float*)d_in[9];
    const float* bl = (const float*)d_in[10];
    float* out = (float*)d_out;

    float *dH, *dA, *dB, *dC;
    float *dS1, *dS2, *dS3, *dS4, *dUx, *dU1, *dU2, *dU3, *dU4;
    __half *dHh, *dAh, *dBh, *dCh;
    cudaGetSymbolAddress((void**)&dH,  g_H);
    cudaGetSymbolAddress((void**)&dA,  g_A);
    cudaGetSymbolAddress((void**)&dB,  g_B);
    cudaGetSymbolAddress((void**)&dC,  g_C);
    cudaGetSymbolAddress((void**)&dHh, g_Hh);
    cudaGetSymbolAddress((void**)&dAh, g_Ah);
    cudaGetSymbolAddress((void**)&dBh, g_Bh);
    cudaGetSymbolAddress((void**)&dCh, g_Ch);
    cudaGetSymbolAddress((void**)&dS1, g_s1);
    cudaGetSymbolAddress((void**)&dS2, g_s2);
    cudaGetSymbolAddress((void**)&dS3, g_s3);
    cudaGetSymbolAddress((void**)&dS4, g_s4);
    cudaGetSymbolAddress((void**)&dUx, g_ux);
    cudaGetSymbolAddress((void**)&dU1, g_u1);
    cudaGetSymbolAddress((void**)&dU2, g_u2);
    cudaGetSymbolAddress((void**)&dU3, g_u3);
    cudaGetSymbolAddress((void**)&dU4, g_u4);

    // CSR build -- profiling probe stays at launch index 3 (ncu -s slot).
    // Probe now covers 1/4 of all nodes with 512 blocks (~1 full wave at
    // 3 blocks/SM) so its counters reflect the saturated full-grid regime.
    // Probe reads prev-replay CSR (zeroed on very first call -> no-op there);
    // writes only g_A/g_Ah/g_O regions fully overwritten before any later read.
    k_zero   <<<NN / 256, 256>>>();
    k_hist   <<<EE / 256, 256>>>(ei);
    k_scan1  <<<64, 1024>>>();                              // + quad-max cnt8 + dinv
    k_prop32<false><<<512, 256>>>(dHh, nullptr, dA, dAh, W2);  // idx 3: PROBE (1/4)
    k_scan3  <<<NN / 256, 256>>>(x);                        // prefix + pad + u_x
    k_scatter<<<EE / 256, 256>>>(ei);

    // layer 1 (scalar Chebyshev recurrence on premultiplied values)
    k_sprop<false><<<NN / 8, 256>>>(dUx, nullptr, dS1, dU1);
    k_sprop<true> <<<NN / 8, 256>>>(dU1, x,       dS2, dU2);
    k_sprop<true> <<<NN / 8, 256>>>(dU2, dS1,     dS3, dU3);
    k_sprop<true> <<<NN / 8, 256>>>(dU3, dS2,     dS4, dU4);
    k_l1init<<<NN / 8, 256>>>(x, W1, b1, W2);

    // layer 2 (quad-node prop: NN/4 warps -> NN/32 blocks)
    k_prop32<false> <<<NN / 32, 256>>>(dHh, nullptr, dA, dAh, W2 + 1 * 1024);
    k_prop32<true>  <<<NN / 32, 256>>>(dAh, dH,      dB, dBh, W2 + 2 * 1024);
    k_prop32<true>  <<<NN / 32, 256>>>(dBh, dA,      dC, dCh, W2 + 3 * 1024);
    k_prop32<true>  <<<NN / 32, 256>>>(dCh, dB,      dA, dAh, W2 + 4 * 1024);
    k_finit<<<NN / 8, 256>>>(b2, W3);   // relu + layer-3 init

    // layer 3
    k_prop32<false> <<<NN / 32, 256>>>(dHh, nullptr, dA, dAh, W3 + 1 * 1024);
    k_prop32<true>  <<<NN / 32, 256>>>(dAh, dH,      dB, dBh, W3 + 2 * 1024);
    k_prop32<true>  <<<NN / 32, 256>>>(dBh, dA,      dC, dCh, W3 + 3 * 1024);
    k_prop32<true>  <<<NN / 32, 256>>>(dCh, dB,      dA, dAh, W3 + 4 * 1024);

    // readout (b3 folded into k_linear)
    k_obias <<<1, 288>>>(bl, out);
    k_linear<<<(ISZ * HID) / 128, 288>>>(Wl, b3, out);
}

// round 12
// speedup vs baseline: 1.0697x; 1.0697x over previous
#include <cuda_runtime.h>
#include <cuda_fp16.h>

#define NN 65536
#define EE 2097152
#define EPAD (2 * EE + 16 * NN)
#define HID 32
#define NG 8
#define OC 33
#define ISZ 8192

// ---------------- scratch (static device allocations only) ----------------
__device__ int   g_deg[NN];
__device__ float g_dinv[NN];
__device__ int   g_cnt[NN];      // raw dst-degree
__device__ int   g_cnt8[NN];     // pair-equalized, padded to multiple of 8
__device__ int   g_rowptr[NN];   // exclusive scan of padded counts (mult of 8)
__device__ int   g_wp[NN];
__device__ int   g_bsum[64];
__device__ __align__(16) int g_esrc[EPAD];   // src-only edges (norm factored out)
// scalar t values (fp32) and premultiplied gather values u = dinv*t (fp32)
__device__ float g_s1[NN], g_s2[NN], g_s3[NN], g_s4[NN];
__device__ float g_ux[NN + 8], g_u1[NN + 8], g_u2[NN + 8], g_u3[NN + 8], g_u4[NN + 8];
__device__ __align__(128) float g_H[NN * HID];
__device__ __align__(128) float g_A[NN * HID];
__device__ __align__(128) float g_B[NN * HID];
__device__ __align__(128) float g_C[NN * HID];
__device__ __align__(128) float g_O[NN * HID];
// fp16 premultiplied gather mirrors: row i < NN holds dinv[i]*t[i]; rows >= NN
// are NEVER written -> remain statically zero-initialized (pad sentinel src=NN)
__device__ __align__(128) __half g_Hh[(NN + 8) * HID];
__device__ __align__(128) __half g_Ah[(NN + 8) * HID];
__device__ __align__(128) __half g_Bh[(NN + 8) * HID];
__device__ __align__(128) __half g_Ch[(NN + 8) * HID];

// ---------------- CSR build ----------------
__global__ void k_zero() {
    int i = blockIdx.x * blockDim.x + threadIdx.x;
    if (i < NN) { g_deg[i] = 0; g_cnt[i] = 0; }
}

__global__ void k_hist(const int* __restrict__ ei) {
    int e = blockIdx.x * blockDim.x + threadIdx.x;
    if (e < EE) {
        atomicAdd(&g_deg[ei[e]], 1);        // degree by src
        atomicAdd(&g_cnt[ei[EE + e]], 1);   // histogram by dst
    }
}

// block-level inclusive scan of pair-equalized padded counts + fused dinv.
// Node pair (2k, 2k+1) both get align8(max(cnt[2k], cnt[2k+1])) slots so the
// dual-node prop loop needs no per-node predication.
__global__ void k_scan1() {
    __shared__ int wsum[32];
    int t = threadIdx.x, b = blockIdx.x;
    int i = b * 1024 + t;
    int lane = t & 31, w = t >> 5;
    int d = g_deg[i];
    g_dinv[i] = (d > 0) ? rsqrtf((float)d) : 0.0f;

    int ca = g_cnt[i];
    int cb = g_cnt[i ^ 1];                  // pair partner (same block)
    int cm = ca > cb ? ca : cb;
    int cntp = (cm + 7) & ~7;
    g_cnt8[i] = cntp;

    int x = cntp;
    #pragma unroll
    for (int o = 1; o < 32; o <<= 1) {
        int y = __shfl_up_sync(0xffffffffu, x, o);
        if (lane >= o) x += y;
    }
    if (lane == 31) wsum[w] = x;
    __syncthreads();
    if (w == 0) {
        int s = wsum[lane];
        #pragma unroll
        for (int o = 1; o < 32; o <<= 1) {
            int y = __shfl_up_sync(0xffffffffu, s, o);
            if (lane >= o) s += y;
        }
        wsum[lane] = s;
    }
    __syncthreads();
    int incl = x + (w > 0 ? wsum[w - 1] : 0);
    g_rowptr[i] = incl;                 // inclusive-within-block (temp)
    if (t == 1023) g_bsum[b] = incl;
}

// finalize rowptr (cross-block prefix inline), fill pad slots, compute u_x
__global__ void k_scan3(const float* __restrict__ x) {
    __shared__ int prefix;
    int i = blockIdx.x * 256 + threadIdx.x;
    if (threadIdx.x == 0) {
        int bchunk = blockIdx.x >> 2;   // 1024-node chunks
        int s = 0;
        for (int j = 0; j < bchunk; j++) s += g_bsum[j];
        prefix = s;
    }
    __syncthreads();
    int excl = g_rowptr[i] - g_cnt8[i] + prefix;   // multiple of 8
    g_rowptr[i] = excl;
    g_wp[i] = excl;
    g_ux[i] = g_dinv[i] * x[i];
    int c = g_cnt[i], cp = g_cnt8[i];
    for (int j = excl + c; j < excl + cp; j++) g_esrc[j] = NN;  // zero-row sentinel
}

__global__ void k_scatter(const int* __restrict__ ei) {
    int e = blockIdx.x * blockDim.x + threadIdx.x;
    if (e < EE) {
        int d = ei[EE + e];
        int pos = atomicAdd(&g_wp[d], 1);
        g_esrc[pos] = ei[e];
    }
}

// ---------------- layer 1 (scalar features, premultiplied gathers) ----------------
// FOUR nodes per warp, 8 lanes each: full lane utilization + 4x overhead amortization.
template <bool PREV>
__global__ void k_sprop(const float* __restrict__ uin,
                        const float* __restrict__ sprev,
                        float* __restrict__ sout,
                        float* __restrict__ usout) {
    int warp = (blockIdx.x * blockDim.x + threadIdx.x) >> 5;
    int lane = threadIdx.x & 31;
    int sub = lane & 7;                      // lane within 8-lane group
    int node = warp * 4 + (lane >> 3);       // group -> node
    int beg = g_rowptr[node], c = g_cnt8[node];
    float acc = 0.0f;
    for (int j = sub * 2; j < c; j += 16) {
        int2 s2 = *reinterpret_cast<const int2*>(g_esrc + beg + j);
        acc += __ldg(&uin[s2.x]) + __ldg(&uin[s2.y]);
    }
    #pragma unroll
    for (int o = 4; o; o >>= 1) acc += __shfl_xor_sync(0xffffffffu, acc, o);
    if (sub == 0) {
        float dd = g_dinv[node];
        float p = -dd * acc;
        float tn = PREV ? (2.0f * p - sprev[node]) : p;
        sout[node] = tn;
        usout[node] = dd * tn;
    }
}

// layer-1 combine + layer-2 init: h = relu(b1 + sum_k s_k*W1[k]); H=h; Hh=dinv*h; O = h @ W2[0]
__global__ void __launch_bounds__(256, 6) k_l1init(const float* __restrict__ x,
                                                   const float* __restrict__ W1,
                                                   const float* __restrict__ b1,
                                                   const float* __restrict__ W20) {
    __shared__ float Ws[1024];
    int tid = threadIdx.x;
    for (int j = tid; j < 1024; j += 256) Ws[j] = W20[j];
    __syncthreads();
    int gw = (blockIdx.x * 256 + tid) >> 5;
    int lane = tid & 31;
    float v = b1[lane]
            + x[gw]      * W1[lane]
            + g_s1[gw]   * W1[32 + lane]
            + g_s2[gw]   * W1[64 + lane]
            + g_s3[gw]   * W1[96 + lane]
            + g_s4[gw]   * W1[128 + lane];
    float h = fmaxf(v, 0.0f);
    g_H[gw * HID + lane] = h;
    g_Hh[gw * HID + lane] = __float2half(g_dinv[gw] * h);
    float oacc = 0.0f;
    #pragma unroll
    for (int j = 0; j < 32; j++)
        oacc = fmaf(__shfl_sync(0xffffffffu, h, j), Ws[j * 32 + lane], oacc);
    g_O[gw * HID + lane] = oacc;
}

// ---------------- layers 2/3 (32-wide), TWO nodes per warp ----------------
// tin holds u = dinv*t (fp16). For each of the warp's two nodes:
// acc = sum u[src]; p = -dinv*acc; t_new = (PREV ? 2p - tprev : p);
// tout = t_new; touth = dinv*t_new; g_O += t_new @ Wk.
// Pair-equalized 8-padded lists -> branch-free loop, 16 independent gathers/iter.
// (256,5): 40 warps/SM -> 640 gathers in flight per SM.
template <bool PREV>
__global__ void __launch_bounds__(256, 5) k_prop32(const __half* __restrict__ tin,
                                                   const float* __restrict__ tprev,
                                                   float* __restrict__ tout,
                                                   __half* __restrict__ touth,
                                                   const float* __restrict__ Wk) {
    __shared__ float Ws[1024];
    int tid = threadIdx.x;
    for (int j = tid; j < 1024; j += 256) Ws[j] = Wk[j];
    __syncthreads();
    int warp = (blockIdx.x * 256 + tid) >> 5;
    int g0 = warp * 2, g1 = g0 + 1;
    int lane = tid & 31;
    const int4* p0 = reinterpret_cast<const int4*>(g_esrc + g_rowptr[g0]);
    const int4* p1 = reinterpret_cast<const int4*>(g_esrc + g_rowptr[g1]);
    int nIter = g_cnt8[g0] >> 3;            // == g_cnt8[g1] >> 3 (pair-equalized)
    float acc0 = 0.0f, acc1 = 0.0f;
    for (int it = 0; it < nIter; it++) {
        int4 ea = p0[0], eb = p0[1];
        int4 ec = p1[0], ed = p1[1];
        p0 += 2; p1 += 2;
        __half a0 = __ldg(&tin[ea.x * HID + lane]);
        __half a1 = __ldg(&tin[ea.y * HID + lane]);
        __half a2 = __ldg(&tin[ea.z * HID + lane]);
        __half a3 = __ldg(&tin[ea.w * HID + lane]);
        __half a4 = __ldg(&tin[eb.x * HID + lane]);
        __half a5 = __ldg(&tin[eb.y * HID + lane]);
        __half a6 = __ldg(&tin[eb.z * HID + lane]);
        __half a7 = __ldg(&tin[eb.w * HID + lane]);
        __half b0 = __ldg(&tin[ec.x * HID + lane]);
        __half b1 = __ldg(&tin[ec.y * HID + lane]);
        __half b2 = __ldg(&tin[ec.z * HID + lane]);
        __half b3 = __ldg(&tin[ec.w * HID + lane]);
        __half b4 = __ldg(&tin[ed.x * HID + lane]);
        __half b5 = __ldg(&tin[ed.y * HID + lane]);
        __half b6 = __ldg(&tin[ed.z * HID + lane]);
        __half b7 = __ldg(&tin[ed.w * HID + lane]);
        acc0 += ((__half2float(a0) + __half2float(a1))
               + (__half2float(a2) + __half2float(a3)))
              + ((__half2float(a4) + __half2float(a5))
               + (__half2float(a6) + __half2float(a7)));
        acc1 += ((__half2float(b0) + __half2float(b1))
               + (__half2float(b2) + __half2float(b3)))
              + ((__half2float(b4) + __half2float(b5))
               + (__half2float(b6) + __half2float(b7)));
    }
    float dd0 = g_dinv[g0], dd1 = g_dinv[g1];
    float pr0 = -dd0 * acc0, pr1 = -dd1 * acc1;
    float tn0, tn1;
    if (PREV) {
        tn0 = 2.0f * pr0 - tprev[g0 * HID + lane];
        tn1 = 2.0f * pr1 - tprev[g1 * HID + lane];
    } else {
        tn0 = pr0; tn1 = pr1;
    }
    tout[g0 * HID + lane] = tn0;
    tout[g1 * HID + lane] = tn1;
    touth[g0 * HID + lane] = __float2half(dd0 * tn0);
    touth[g1 * HID + lane] = __float2half(dd1 * tn1);
    float o0 = g_O[g0 * HID + lane];
    float o1 = g_O[g1 * HID + lane];
    #pragma unroll
    for (int j = 0; j < 32; j++) {
        float w = Ws[j * 32 + lane];
        o0 = fmaf(__shfl_sync(0xffffffffu, tn0, j), w, o0);
        o1 = fmaf(__shfl_sync(0xffffffffu, tn1, j), w, o1);
    }
    g_O[g0 * HID + lane] = o0;
    g_O[g1 * HID + lane] = o1;
}

// finalize layer L + init layer L+1: h = relu(O + b); H=h; Hh=dinv*h; O = h @ Wn0
__global__ void __launch_bounds__(256, 6) k_finit(const float* __restrict__ b,
                                                  const float* __restrict__ Wn0) {
    __shared__ float Ws[1024];
    int tid = threadIdx.x;
    for (int j = tid; j < 1024; j += 256) Ws[j] = Wn0[j];
    __syncthreads();
    int gw = (blockIdx.x * 256 + tid) >> 5;
    int lane = tid & 31;
    float h = fmaxf(g_O[gw * HID + lane] + b[lane], 0.0f);
    g_H[gw * HID + lane] = h;
    g_Hh[gw * HID + lane] = __float2half(g_dinv[gw] * h);
    float oacc = 0.0f;
    #pragma unroll
    for (int j = 0; j < 32; j++)
        oacc = fmaf(__shfl_sync(0xffffffffu, h, j), Ws[j * 32 + lane], oacc);
    g_O[gw * HID + lane] = oacc;
}

// ---------------- final linear: (8, 262144) @ (262144, 33) + bl ----------------
// layer-3 bias b3 folded in (h = O + b3); no separate finalize pass.
__global__ void k_obias(const float* __restrict__ bl, float* __restrict__ out) {
    int i = threadIdx.x;
    if (i < NG * OC) out[i] = bl[i % OC];
}

__global__ void __launch_bounds__(288) k_linear(const float* __restrict__ Wl,
                                                const float* __restrict__ b3,
                                                float* __restrict__ out) {
    __shared__ float Ws[128 * OC];   // 16896 B
    __shared__ float hs[NG * 128];   //  4096 B
    int t = threadIdx.x;
    int i0 = blockIdx.x * 128;
    for (int j = t; j < 128 * OC; j += 288) Ws[j] = Wl[i0 * OC + j];
    for (int j = t; j < NG * 128; j += 288) {
        int g = j >> 7, ii = j & 127;
        hs[j] = g_O[g * (ISZ * HID) + i0 + ii] + b3[(i0 + ii) & 31];
    }
    __syncthreads();
    if (t < NG * OC) {
        int g = t / OC, o = t % OC;
        float acc = 0.0f;
        #pragma unroll 8
        for (int ii = 0; ii < 128; ii++)
            acc = fmaf(hs[g * 128 + ii], Ws[ii * OC + o], acc);
        atomicAdd(&out[g * OC + o], acc);
    }
}

// ---------------- host ----------------
extern "C" void kernel_launch(void* const* d_in, const int* in_sizes, int n_in,
                              void* d_out, int out_size) {
    const float* x  = (const float*)d_in[0];
    const int*   ei = (const int*)  d_in[1];
    const float* W1 = (const float*)d_in[3];
    const float* b1 = (const float*)d_in[4];
    const float* W2 = (const float*)d_in[5];
    const float* b2 = (const float*)d_in[6];
    const float* W3 = (const float*)d_in[7];
    const float* b3 = (const float*)d_in[8];
    const float* Wl = (const float*)d_in[9];
    const float* bl = (const float*)d_in[10];
    float* out = (float*)d_out;

    float *dH, *dA, *dB, *dC;
    float *dS1, *dS2, *dS3, *dS4, *dUx, *dU1, *dU2, *dU3, *dU4;
    __half *dHh, *dAh, *dBh, *dCh;
    cudaGetSymbolAddress((void**)&dH,  g_H);
    cudaGetSymbolAddress((void**)&dA,  g_A);
    cudaGetSymbolAddress((void**)&dB,  g_B);
    cudaGetSymbolAddress((void**)&dC,  g_C);
    cudaGetSymbolAddress((void**)&dHh, g_Hh);
    cudaGetSymbolAddress((void**)&dAh, g_Ah);
    cudaGetSymbolAddress((void**)&dBh, g_Bh);
    cudaGetSymbolAddress((void**)&dCh, g_Ch);
    cudaGetSymbolAddress((void**)&dS1, g_s1);
    cudaGetSymbolAddress((void**)&dS2, g_s2);
    cudaGetSymbolAddress((void**)&dS3, g_s3);
    cudaGetSymbolAddress((void**)&dS4, g_s4);
    cudaGetSymbolAddress((void**)&dUx, g_ux);
    cudaGetSymbolAddress((void**)&dU1, g_u1);
    cudaGetSymbolAddress((void**)&dU2, g_u2);
    cudaGetSymbolAddress((void**)&dU3, g_u3);
    cudaGetSymbolAddress((void**)&dU4, g_u4);

    // CSR build (profiling probe removed -- evidence phase done)
    k_zero   <<<NN / 256, 256>>>();
    k_hist   <<<EE / 256, 256>>>(ei);
    k_scan1  <<<64, 1024>>>();                              // + pair-max cnt8 + dinv
    k_scan3  <<<NN / 256, 256>>>(x);                        // prefix + pad + u_x
    k_scatter<<<EE / 256, 256>>>(ei);

    // layer 1 (scalar Chebyshev recurrence, 4 nodes/warp)
    k_sprop<false><<<NN / 32, 256>>>(dUx, nullptr, dS1, dU1);
    k_sprop<true> <<<NN / 32, 256>>>(dU1, x,       dS2, dU2);
    k_sprop<true> <<<NN / 32, 256>>>(dU2, dS1,     dS3, dU3);
    k_sprop<true> <<<NN / 32, 256>>>(dU3, dS2,     dS4, dU4);
    k_l1init<<<NN / 8, 256>>>(x, W1, b1, W2);

    // layer 2 (dual-node prop: NN/2 warps -> NN/16 blocks)
    k_prop32<false> <<<NN / 16, 256>>>(dHh, nullptr, dA, dAh, W2 + 1 * 1024);
    k_prop32<true>  <<<NN / 16, 256>>>(dAh, dH,      dB, dBh, W2 + 2 * 1024);
    k_prop32<true>  <<<NN / 16, 256>>>(dBh, dA,      dC, dCh, W2 + 3 * 1024);
    k_prop32<true>  <<<NN / 16, 256>>>(dCh, dB,      dA, dAh, W2 + 4 * 1024);
    k_finit<<<NN / 8, 256>>>(b2, W3);   // relu + layer-3 init

    // layer 3
    k_prop32<false> <<<NN / 16, 256>>>(dHh, nullptr, dA, dAh, W3 + 1 * 1024);
    k_prop32<true>  <<<NN / 16, 256>>>(dAh, dH,      dB, dBh, W3 + 2 * 1024);
    k_prop32<true>  <<<NN / 16, 256>>>(dBh, dA,      dC, dCh, W3 + 3 * 1024);
    k_prop32<true>  <<<NN / 16, 256>>>(dCh, dB,      dA, dAh, W3 + 4 * 1024);

    // readout (b3 folded into k_linear)
    k_obias <<<1, 288>>>(bl, out);
    k_linear<<<(ISZ * HID) / 128, 288>>>(Wl, b3, out);
}